// round 2
// baseline (speedup 1.0000x reference)
#include <cuda_runtime.h>
#include <cuda_bf16.h>

#define NN 100000
#define EE 1600000
#define DD 128

// ---------------- scratch (device globals; no allocations allowed) ----------
__device__ float g_y[(size_t)NN * DD];      // GEMM output (pre-propagation)
__device__ float g_agg[(size_t)NN * DD];    // aggregation output (layer 1)
__device__ float g_dout[NN];                // out-degree norm
__device__ float g_din[NN];                 // in-degree norm
__device__ int   g_degout[NN];
__device__ int   g_degin[NN];
__device__ int   g_rowstart[NN + 1];        // CSR row offsets (by dst)
__device__ int   g_fill[NN];                // atomic cursors for CSR fill
__device__ int   g_csr[EE];                 // src ids, grouped by dst
__device__ int   g_src[EE];
__device__ int   g_dst[EE];
__device__ float g_bw[DD];                  // b1 @ W2
__device__ int   g_is32;

// ---------------- dtype detect: int64 vs int32 edge_index -------------------
// If int64 node ids: every 8-byte word is in [0, NN). If int32 pairs: an int64
// view is (lo | hi<<32) with hi a random node id -> out of range a.s.
__global__ void detect_kernel(const void* ei) {
    __shared__ int bad;
    if (threadIdx.x == 0) bad = 0;
    __syncthreads();
    const long long* p = (const long long*)ei;
    for (int i = threadIdx.x; i < 2048; i += blockDim.x) {
        long long v = p[i];
        if (v < 0 || v >= NN) atomicOr(&bad, 1);
    }
    __syncthreads();
    if (threadIdx.x == 0) g_is32 = bad;
}

// ---------------- zero per-node counters ------------------------------------
__global__ void zero_kernel() {
    int i = blockIdx.x * blockDim.x + threadIdx.x;
    if (i < NN) { g_degout[i] = 0; g_degin[i] = 0; g_fill[i] = 0; }
}

// ---------------- decode edges to int32 + integer degree histogram ----------
__global__ void edges_kernel(const void* ei) {
    int e = blockIdx.x * blockDim.x + threadIdx.x;
    if (e >= EE) return;
    int s, d;
    if (g_is32) {
        const int* p = (const int*)ei;
        s = p[e]; d = p[EE + e];
    } else {
        const long long* p = (const long long*)ei;
        s = (int)p[e]; d = (int)p[EE + e];
    }
    g_src[e] = s; g_dst[e] = d;
    atomicAdd(&g_degout[s], 1);
    atomicAdd(&g_degin[d], 1);
}

__global__ void norm_kernel() {
    int i = blockIdx.x * blockDim.x + threadIdx.x;
    if (i < NN) {
        g_dout[i] = rsqrtf(fmaxf((float)g_degout[i], 1.f));
        g_din[i]  = rsqrtf(fmaxf((float)g_degin[i],  1.f));
    }
}

// ---------------- exclusive scan of in-degrees -> CSR row offsets -----------
// Single block, 1024 threads, chunked: ~98 elements/thread.
__global__ void scan_kernel() {
    __shared__ int sums[1024];
    const int t = threadIdx.x;
    const int CH = (NN + 1023) / 1024;                  // 98
    int lo = t * CH, hi = min(lo + CH, NN);
    int s = 0;
    for (int i = lo; i < hi; i++) s += g_degin[i];
    sums[t] = s;
    __syncthreads();
    for (int off = 1; off < 1024; off <<= 1) {          // inclusive Hillis-Steele
        int v = (t >= off) ? sums[t - off] : 0;
        __syncthreads();
        sums[t] += v;
        __syncthreads();
    }
    int pre = (t == 0) ? 0 : sums[t - 1];               // exclusive prefix of chunk
    for (int i = lo; i < hi; i++) { g_rowstart[i] = pre; pre += g_degin[i]; }
    if (t == 1023) g_rowstart[NN] = sums[1023];         // == EE
}

// ---------------- CSR fill: group src ids by dst -----------------------------
__global__ void fill_kernel() {
    int e = blockIdx.x * blockDim.x + threadIdx.x;
    if (e >= EE) return;
    int d = g_dst[e];
    int pos = atomicAdd(&g_fill[d], 1);
    g_csr[g_rowstart[d] + pos] = g_src[e];
}

// ---------------- bW = b1 @ W2 (tiny) ---------------------------------------
__global__ void bw_kernel(const float* __restrict__ b1, const float* __restrict__ W2) {
    int j = threadIdx.x;
    float s = 0.f;
    for (int k = 0; k < DD; k++) s = fmaf(b1[k], W2[k * DD + j], s);
    g_bw[j] = s;
}

// ---------------- fused GEMM -------------------------------------------------
// layer==1: Y[i,:] = (X[i,:] @ W) * dout[i]
// layer==2: Y[i,:] = ((X[i,:] @ W) + bW) * dout[i]     (X = agg1, din folded)
// Block: 256 threads, 64 rows x 128 cols; each thread 8 rows x 4 cols.
__global__ __launch_bounds__(256, 2) void gemm_kernel(
    const float* __restrict__ X, const float* __restrict__ W,
    float* __restrict__ Y, int layer)
{
    __shared__ float Xs[64][36];    // padded: conflict-light stores
    __shared__ float Ws[32][DD];

    const int tid = threadIdx.x;
    const int i0  = blockIdx.x * 64;
    const int cx  = tid & 31;            // cols cx*4 .. cx*4+3
    const int r0  = (tid >> 5) * 8;      // 8 rows per thread; warp shares r0

    float acc[8][4];
    #pragma unroll
    for (int i = 0; i < 8; i++)
        acc[i][0] = acc[i][1] = acc[i][2] = acc[i][3] = 0.f;

    for (int kc = 0; kc < DD; kc += 32) {
        #pragma unroll
        for (int t = 0; t < 2; t++) {            // X tile: 64 rows x 32 k
            int id = tid + t * 256;
            int r = id >> 3, q = id & 7;
            int row = i0 + r;
            float4 v = make_float4(0.f, 0.f, 0.f, 0.f);
            if (row < NN) v = *(const float4*)(X + (size_t)row * DD + kc + q * 4);
            Xs[r][q * 4 + 0] = v.x; Xs[r][q * 4 + 1] = v.y;
            Xs[r][q * 4 + 2] = v.z; Xs[r][q * 4 + 3] = v.w;
        }
        #pragma unroll
        for (int t = 0; t < 4; t++) {            // W tile: 32 k x 128 cols
            int id = tid + t * 256;
            int k = id >> 5, q = id & 31;
            *(float4*)&Ws[k][q * 4] =
                *(const float4*)(W + (size_t)(kc + k) * DD + q * 4);
        }
        __syncthreads();

        #pragma unroll
        for (int k = 0; k < 32; k++) {
            float4 w = *(const float4*)&Ws[k][cx * 4];
            #pragma unroll
            for (int i = 0; i < 8; i++) {
                float x = Xs[r0 + i][k];         // warp-broadcast LDS
                acc[i][0] = fmaf(x, w.x, acc[i][0]);
                acc[i][1] = fmaf(x, w.y, acc[i][1]);
                acc[i][2] = fmaf(x, w.z, acc[i][2]);
                acc[i][3] = fmaf(x, w.w, acc[i][3]);
            }
        }
        __syncthreads();
    }

    float c0 = 0.f, c1 = 0.f, c2 = 0.f, c3 = 0.f;
    if (layer == 2) {
        c0 = g_bw[cx * 4 + 0]; c1 = g_bw[cx * 4 + 1];
        c2 = g_bw[cx * 4 + 2]; c3 = g_bw[cx * 4 + 3];
    }
    #pragma unroll
    for (int i = 0; i < 8; i++) {
        int row = i0 + r0 + i;
        if (row < NN) {
            float po = g_dout[row];
            float4 o;
            o.x = (acc[i][0] + c0) * po;
            o.y = (acc[i][1] + c1) * po;
            o.z = (acc[i][2] + c2) * po;
            o.w = (acc[i][3] + c3) * po;
            *(float4*)(Y + (size_t)row * DD + cx * 4) = o;
        }
    }
}

// ---------------- CSR-gather aggregation -------------------------------------
// One warp per dst node: Out[i,:] = din[i] * sum_{e in in(i)} Y[csr[e], :] (+bias)
// Lane j holds float4 at cols j*4..j*4+3; each row read is 512 B coalesced.
__global__ __launch_bounds__(256) void aggregate_kernel(
    const float* __restrict__ Yin, float* __restrict__ Out,
    const float* __restrict__ bias)
{
    int warp = (int)((blockIdx.x * blockDim.x + threadIdx.x) >> 5);
    if (warp >= NN) return;
    const int lane = threadIdx.x & 31;
    const int s0 = g_rowstart[warp];
    const int s1 = g_rowstart[warp + 1];

    float4 acc = make_float4(0.f, 0.f, 0.f, 0.f);
    int e = s0;
    for (; e + 4 <= s1; e += 4) {                 // unroll 4 for MLP
        int a = g_csr[e], b = g_csr[e + 1], c = g_csr[e + 2], d = g_csr[e + 3];
        float4 va = *(const float4*)(Yin + (size_t)a * DD + lane * 4);
        float4 vb = *(const float4*)(Yin + (size_t)b * DD + lane * 4);
        float4 vc = *(const float4*)(Yin + (size_t)c * DD + lane * 4);
        float4 vd = *(const float4*)(Yin + (size_t)d * DD + lane * 4);
        acc.x += (va.x + vb.x) + (vc.x + vd.x);
        acc.y += (va.y + vb.y) + (vc.y + vd.y);
        acc.z += (va.z + vb.z) + (vc.z + vd.z);
        acc.w += (va.w + vb.w) + (vc.w + vd.w);
    }
    for (; e < s1; e++) {
        int a = g_csr[e];
        float4 va = *(const float4*)(Yin + (size_t)a * DD + lane * 4);
        acc.x += va.x; acc.y += va.y; acc.z += va.z; acc.w += va.w;
    }

    float dn = g_din[warp];
    float4 bb = make_float4(0.f, 0.f, 0.f, 0.f);
    if (bias) bb = *(const float4*)(bias + lane * 4);
    float4 o;
    o.x = fmaf(acc.x, dn, bb.x);
    o.y = fmaf(acc.y, dn, bb.y);
    o.z = fmaf(acc.z, dn, bb.z);
    o.w = fmaf(acc.w, dn, bb.w);
    *(float4*)(Out + (size_t)warp * DD + lane * 4) = o;
}

// ---------------- launch ------------------------------------------------------
extern "C" void kernel_launch(void* const* d_in, const int* in_sizes, int n_in,
                              void* d_out, int out_size) {
    const float* in_feat = (const float*)d_in[0];
    const void*  ei      = d_in[1];
    const float* W1      = (const float*)d_in[2];
    const float* b1      = (const float*)d_in[3];
    const float* W2      = (const float*)d_in[4];
    const float* b2      = (const float*)d_in[5];
    float*       out     = (float*)d_out;

    const int n_blocks    = (NN + 255) / 256;          // 391
    const int e_blocks    = (EE + 255) / 256;          // 6250
    const int gemm_blocks = (NN + 63) / 64;            // 1563
    const int agg_blocks  = (NN * 32 + 255) / 256;     // 12500 (1 warp/node)

    // --- graph preprocessing: decode, degrees, norms, CSR ---
    detect_kernel<<<1, 256>>>(ei);
    zero_kernel<<<n_blocks, 256>>>();
    edges_kernel<<<e_blocks, 256>>>(ei);
    norm_kernel<<<n_blocks, 256>>>();
    scan_kernel<<<1, 1024>>>();
    fill_kernel<<<e_blocks, 256>>>();
    bw_kernel<<<1, DD>>>(b1, W2);

    // --- layer 1: y1 = (X@W1)*dout ; agg1 = din * S(y1)  (b1 deferred via bW) ---
    gemm_kernel<<<gemm_blocks, 256>>>(in_feat, W1, g_y, 1);
    aggregate_kernel<<<agg_blocks, 256>>>(g_y, g_agg, nullptr);

    // --- layer 2: y2 = (agg1@W2 + b1@W2)*dout ; out = din * S(y2) + b2 ---
    gemm_kernel<<<gemm_blocks, 256>>>(g_agg, W2, g_y, 2);
    aggregate_kernel<<<agg_blocks, 256>>>(g_y, out, b2);
}